// round 4
// baseline (speedup 1.0000x reference)
#include <cuda_runtime.h>
#include <cstdint>
#include <math.h>

// Problem constants
#define B_      4
#define S_      4096
#define DIN     1024
#define NC      1024
#define N1      2048
#define M_      (B_*S_)         // 16384
#define LANES   (B_*NC)         // 4096
#define NCHUNK  64
#define LC      (S_/NCHUNK)     // 64

// ---------------- scratch (static device globals) ----------------
__device__ uint32_t g_W1T[(size_t)N1 * DIN];      // packed weights, [n][k], PRE-CONVERTED tf32 bits
__device__ uint32_t g_WgT[(size_t)NC * DIN];      // gate weights, [n][k], tf32 bits
__device__ float    g_b1[N1];
__device__ float    g_Y[(size_t)M_ * N1];         // interleaved (a,b) pairs for the scan
__device__ float    g_h[(size_t)M_ * NC];
__device__ float2   g_Agg[NCHUNK * LANES];
__device__ float    g_Carry[NCHUNK * LANES];

__device__ __forceinline__ float sigmoidf_(float x) { return 1.0f / (1.0f + __expf(-x)); }
__device__ __forceinline__ uint32_t f2tf(float f) {
    uint32_t r;
    asm("cvt.rna.tf32.f32 %0, %1;" : "=r"(r) : "f"(f));
    return r;
}

__device__ __forceinline__ void mma_tf32(float c[4],
                                         uint32_t a0, uint32_t a1, uint32_t a2, uint32_t a3,
                                         uint32_t b0, uint32_t b1) {
    asm volatile(
        "mma.sync.aligned.m16n8k8.row.col.f32.tf32.tf32.f32 "
        "{%0,%1,%2,%3}, {%4,%5,%6,%7}, {%8,%9}, {%0,%1,%2,%3};"
        : "+f"(c[0]), "+f"(c[1]), "+f"(c[2]), "+f"(c[3])
        : "r"(a0), "r"(a1), "r"(a2), "r"(a3), "r"(b0), "r"(b1));
}

// ---------------- weight transpose / pack (emits tf32 bit patterns) ----------------
// which==0: dst=g_W1T ; which==1: dst=g_WgT
// dst[(nOff + nMul*c) * 1024 + k] = tf32(src[k * Cdim + c])
__global__ void transpose_pack_kernel(const float* __restrict__ src,
                                      int Cdim, int nMul, int nOff, int which) {
    __shared__ float sm[32][33];
    uint32_t* dst = which ? g_WgT : g_W1T;
    int c0 = blockIdx.x * 32;
    int k0 = blockIdx.y * 32;
    int tx = threadIdx.x, ty = threadIdx.y;
    sm[ty][tx] = src[(size_t)(k0 + ty) * Cdim + c0 + tx];
    __syncthreads();
    int n = nOff + nMul * (c0 + ty);
    dst[(size_t)n * 1024 + k0 + tx] = f2tf(sm[tx][ty]);
}

__global__ void pack_bias_kernel(const float* __restrict__ bzf, const float* __restrict__ bhf,
                                 const float* __restrict__ bzs, const float* __restrict__ bhs) {
    int n = blockIdx.x * 256 + threadIdx.x;
    if (n >= N1) return;
    int c = n >> 1, hp = n & 1;
    float v;
    if (c < 512) v = hp ? bhf[c]       : bzf[c];
    else         v = hp ? bhs[c - 512] : bzs[c - 512];
    g_b1[n] = v;
}

// ---------------- tf32 mma.sync GEMM: 128x128 CTA, BK=16, 4 warps (64x64 each) ----------------
// SMEM tile layout (paired-k for LDS.64):
//   element (k, col) -> buf[kk2*KK2STR + t*TSTR + 2*col + p],  kk2=k>>3, p=(k>>2)&1, t=k&3
//   TSTR=264 (mod 32 = 8 words), KK2STR=1072 (mod 32 = 16 words)
//   -> fragment LDS.64 and scatter STS.32 both provably bank-conflict-free.
#define TSTR   264
#define KK2STR 1072
#define BUFSZ  2144            // 2*KK2STR uint32 per buffer

template <int MODE>   // 1 = GEMM1 (scan-coeff epilogue), 2 = GEMM2 (gated-output epilogue)
__device__ __forceinline__ void gemm_core(const float* __restrict__ A,
                                          const uint32_t* __restrict__ BT,
                                          const float* __restrict__ bias,
                                          float* __restrict__ Out) {
    __shared__ uint32_t sA[2][BUFSZ];
    __shared__ uint32_t sB[2][BUFSZ];

    const int tid  = threadIdx.x;
    const int lane = tid & 31, w = tid >> 5;
    const int g = lane >> 2, t = lane & 3;
    const int wm = (w & 1) * 64, wn = (w >> 1) * 64;
    const int bm = blockIdx.y * 128, bn = blockIdx.x * 128;
    const int mrow = tid >> 2;     // 0..31 (+32*i)
    const int kq   = tid & 3;      // k-quad within the 16-wide chunk

    const float*    Ag = A  + (size_t)bm * 1024 + kq * 4;
    const uint32_t* Bg = BT + (size_t)bn * 1024 + kq * 4;

    // store index base for this thread (j indexes the 4 k's in its quad)
    const int stBase = (kq >> 1) * KK2STR + (kq & 1);   // + j*TSTR + 2*m

    float acc[4][8][4];
#pragma unroll
    for (int i = 0; i < 4; i++)
#pragma unroll
        for (int j = 0; j < 8; j++)
#pragma unroll
            for (int q = 0; q < 4; q++) acc[i][j][q] = 0.0f;

    uint32_t stA[4][4];   // staged tf32 bits, [i][j]
    uint4    stB[4];

    // prologue: load + stage chunk 0, store into buf 0
#pragma unroll
    for (int i = 0; i < 4; i++) {
        int m = mrow + 32 * i;
        float4 av = *(const float4*)(Ag + (size_t)m * 1024);
        stA[i][0] = f2tf(av.x); stA[i][1] = f2tf(av.y);
        stA[i][2] = f2tf(av.z); stA[i][3] = f2tf(av.w);
        stB[i] = *(const uint4*)(Bg + (size_t)m * 1024);
    }
#pragma unroll
    for (int i = 0; i < 4; i++) {
        int m2 = 2 * (mrow + 32 * i);
        sA[0][stBase + 0 * TSTR + m2] = stA[i][0];
        sA[0][stBase + 1 * TSTR + m2] = stA[i][1];
        sA[0][stBase + 2 * TSTR + m2] = stA[i][2];
        sA[0][stBase + 3 * TSTR + m2] = stA[i][3];
        sB[0][stBase + 0 * TSTR + m2] = stB[i].x;
        sB[0][stBase + 1 * TSTR + m2] = stB[i].y;
        sB[0][stBase + 2 * TSTR + m2] = stB[i].z;
        sB[0][stBase + 3 * TSTR + m2] = stB[i].w;
    }
    __syncthreads();

    for (int kt = 0; kt < 64; kt++) {
        const int p = kt & 1;
        // prefetch + stage next chunk (overlaps with compute below)
        if (kt < 63) {
#pragma unroll
            for (int i = 0; i < 4; i++) {
                int m = mrow + 32 * i;
                float4 av = *(const float4*)(Ag + (size_t)m * 1024 + (kt + 1) * 16);
                stA[i][0] = f2tf(av.x); stA[i][1] = f2tf(av.y);
                stA[i][2] = f2tf(av.z); stA[i][3] = f2tf(av.w);
                stB[i] = *(const uint4*)(Bg + (size_t)m * 1024 + (kt + 1) * 16);
            }
        }
        // compute on buffer p: pure LDS.64 + HMMA
#pragma unroll
        for (int kk2 = 0; kk2 < 2; kk2++) {
            const int base = kk2 * KK2STR + t * TSTR;
            uint2 bf[8];
#pragma unroll
            for (int nt = 0; nt < 8; nt++) {
                int n = wn + nt * 8 + g;
                bf[nt] = *(const uint2*)&sB[p][base + 2 * n];
            }
#pragma unroll
            for (int mt = 0; mt < 4; mt++) {
                int m = wm + mt * 16 + g;
                uint2 va = *(const uint2*)&sA[p][base + 2 * m];
                uint2 vb = *(const uint2*)&sA[p][base + 2 * (m + 8)];
#pragma unroll
                for (int nt = 0; nt < 8; nt++)
                    mma_tf32(acc[mt][nt], va.x, vb.x, va.y, vb.y, bf[nt].x, bf[nt].y);
            }
        }
        // store staged chunk into the other buffer (no WAR race: compute used buf p)
        if (kt < 63) {
            const int q = p ^ 1;
#pragma unroll
            for (int i = 0; i < 4; i++) {
                int m2 = 2 * (mrow + 32 * i);
                sA[q][stBase + 0 * TSTR + m2] = stA[i][0];
                sA[q][stBase + 1 * TSTR + m2] = stA[i][1];
                sA[q][stBase + 2 * TSTR + m2] = stA[i][2];
                sA[q][stBase + 3 * TSTR + m2] = stA[i][3];
                sB[q][stBase + 0 * TSTR + m2] = stB[i].x;
                sB[q][stBase + 1 * TSTR + m2] = stB[i].y;
                sB[q][stBase + 2 * TSTR + m2] = stB[i].z;
                sB[q][stBase + 3 * TSTR + m2] = stB[i].w;
            }
            __syncthreads();
        }
    }

    // ---------------- epilogue ----------------
    const int NOUT = (MODE == 1) ? N1 : NC;
#pragma unroll
    for (int mt = 0; mt < 4; mt++) {
#pragma unroll
        for (int nt = 0; nt < 8; nt++) {
            int row = bm + wm + mt * 16 + g;
            int col = bn + wn + nt * 8 + t * 2;       // even: one (z, h~) pair
            float2 bb = *(const float2*)&bias[col];
            const float* a4 = acc[mt][nt];
            if (MODE == 1) {
                float z0 = sigmoidf_(a4[0] + bb.x);
                float h0 = a4[1] + bb.y;
                *(float2*)&Out[(size_t)row * NOUT + col] = make_float2(1.0f - z0, z0 * h0);
                float z1 = sigmoidf_(a4[2] + bb.x);
                float h1 = a4[3] + bb.y;
                *(float2*)&Out[(size_t)(row + 8) * NOUT + col] = make_float2(1.0f - z1, z1 * h1);
            } else {
                float2 hv0 = *(const float2*)&g_h[(size_t)row * NC + col];
                *(float2*)&Out[(size_t)row * NOUT + col] =
                    make_float2(hv0.x * sigmoidf_(a4[0] + bb.x),
                                hv0.y * sigmoidf_(a4[1] + bb.y));
                float2 hv1 = *(const float2*)&g_h[(size_t)(row + 8) * NC + col];
                *(float2*)&Out[(size_t)(row + 8) * NOUT + col] =
                    make_float2(hv1.x * sigmoidf_(a4[2] + bb.x),
                                hv1.y * sigmoidf_(a4[3] + bb.y));
            }
        }
    }
}

__global__ __launch_bounds__(128) void gemm1_mma(const float* __restrict__ x) {
    gemm_core<1>(x, g_W1T, g_b1, g_Y);
}
__global__ __launch_bounds__(128) void gemm2_mma(const float* __restrict__ bg,
                                                 float* __restrict__ out) {
    gemm_core<2>(g_h, g_WgT, bg, out);
}

// ---------------- scan (3-phase chunked) ----------------
__global__ __launch_bounds__(256) void scan_phase1() {
    int lane = blockIdx.x * blockDim.x + threadIdx.x;
    int j    = blockIdx.y;
    int b    = lane >> 10;
    int c    = lane & (NC - 1);
    const float2* Y2 = (const float2*)g_Y;
    size_t base = ((size_t)(b * S_ + j * LC)) * NC + c;
    float A = 1.0f, H = 0.0f;
#pragma unroll 8
    for (int t = 0; t < LC; t++) {
        float2 ab = Y2[base + (size_t)t * NC];
        A *= ab.x;
        H = fmaf(ab.x, H, ab.y);
    }
    g_Agg[j * LANES + lane] = make_float2(A, H);
}

__global__ __launch_bounds__(256) void scan_phase2() {
    int lane = blockIdx.x * blockDim.x + threadIdx.x;
    float carry = 0.0f;
#pragma unroll
    for (int j = 0; j < NCHUNK; j++) {
        float2 e = g_Agg[j * LANES + lane];
        g_Carry[j * LANES + lane] = carry;
        carry = fmaf(e.x, carry, e.y);
    }
}

__global__ __launch_bounds__(256) void scan_phase3() {
    int lane = blockIdx.x * blockDim.x + threadIdx.x;
    int j    = blockIdx.y;
    int b    = lane >> 10;
    int c    = lane & (NC - 1);
    const float2* Y2 = (const float2*)g_Y;
    size_t m0 = (size_t)(b * S_ + j * LC);
    size_t base = m0 * NC + c;
    float H = g_Carry[j * LANES + lane];
#pragma unroll 8
    for (int t = 0; t < LC; t++) {
        float2 ab = Y2[base + (size_t)t * NC];
        H = fmaf(ab.x, H, ab.y);
        g_h[(m0 + t) * NC + c] = H;
    }
}

// ---------------- launch ----------------
extern "C" void kernel_launch(void* const* d_in, const int* in_sizes, int n_in,
                              void* d_out, int out_size) {
    const float* x   = (const float*)d_in[0];
    const float* Wzf = (const float*)d_in[1];
    const float* bzf = (const float*)d_in[2];
    const float* Whf = (const float*)d_in[3];
    const float* bhf = (const float*)d_in[4];
    const float* Wzs = (const float*)d_in[5];
    const float* bzs = (const float*)d_in[6];
    const float* Whs = (const float*)d_in[7];
    const float* bhs = (const float*)d_in[8];
    const float* Wg  = (const float*)d_in[9];
    const float* bg  = (const float*)d_in[10];
    float* out = (float*)d_out;

    dim3 tb(32, 32);
    transpose_pack_kernel<<<dim3(16, 32), tb>>>(Wzf, 512, 2, 0, 0);
    transpose_pack_kernel<<<dim3(16, 32), tb>>>(Whf, 512, 2, 1, 0);
    transpose_pack_kernel<<<dim3(16, 32), tb>>>(Wzs, 512, 2, 1024, 0);
    transpose_pack_kernel<<<dim3(16, 32), tb>>>(Whs, 512, 2, 1025, 0);
    transpose_pack_kernel<<<dim3(32, 32), tb>>>(Wg, 1024, 1, 0, 1);
    pack_bias_kernel<<<N1 / 256, 256>>>(bzf, bhf, bzs, bhs);

    gemm1_mma<<<dim3(N1 / 128, M_ / 128), 128>>>(x);

    scan_phase1<<<dim3(LANES / 256, NCHUNK), 256>>>();
    scan_phase2<<<LANES / 256, 256>>>();
    scan_phase3<<<dim3(LANES / 256, NCHUNK), 256>>>();

    gemm2_mma<<<dim3(NC / 128, M_ / 128), 128>>>(bg, out);
}

// round 5
// speedup vs baseline: 1.0081x; 1.0081x over previous
#include <cuda_runtime.h>
#include <cstdint>
#include <math.h>

// Problem constants
#define B_      4
#define S_      4096
#define DIN     1024
#define NC      1024
#define N1      2048
#define M_      (B_*S_)         // 16384
#define LANES   (B_*NC)         // 4096
#define NCHUNK  64
#define LC      (S_/NCHUNK)     // 64

// ---------------- scratch (static device globals) ----------------
__device__ uint32_t g_W1T[(size_t)N1 * DIN];      // packed weights [n][k], PRE-CONVERTED tf32 bits
__device__ uint32_t g_WgT[(size_t)NC * DIN];      // gate weights [n][k], tf32 bits
__device__ float    g_b1[N1];
__device__ float    g_Y[(size_t)M_ * N1];         // interleaved (a,b) pairs for the scan
__device__ float    g_h[(size_t)M_ * NC];
__device__ float2   g_Agg[NCHUNK * LANES];
__device__ float    g_Carry[NCHUNK * LANES];

__device__ __forceinline__ float sigmoidf_(float x) { return 1.0f / (1.0f + __expf(-x)); }
__device__ __forceinline__ uint32_t f2tf(float f) {
    uint32_t r;
    asm("cvt.rna.tf32.f32 %0, %1;" : "=r"(r) : "f"(f));
    return r;
}

__device__ __forceinline__ void mma_tf32(float c[4],
                                         uint32_t a0, uint32_t a1, uint32_t a2, uint32_t a3,
                                         uint32_t b0, uint32_t b1) {
    asm volatile(
        "mma.sync.aligned.m16n8k8.row.col.f32.tf32.tf32.f32 "
        "{%0,%1,%2,%3}, {%4,%5,%6,%7}, {%8,%9}, {%0,%1,%2,%3};"
        : "+f"(c[0]), "+f"(c[1]), "+f"(c[2]), "+f"(c[3])
        : "r"(a0), "r"(a1), "r"(a2), "r"(a3), "r"(b0), "r"(b1));
}

// ---------------- weight transpose / pack (emits tf32 bit patterns) ----------------
// which==0: dst=g_W1T ; which==1: dst=g_WgT
// dst[(nOff + nMul*c) * 1024 + k] = tf32(src[k * Cdim + c])
__global__ void transpose_pack_kernel(const float* __restrict__ src,
                                      int Cdim, int nMul, int nOff, int which) {
    __shared__ float sm[32][33];
    uint32_t* dst = which ? g_WgT : g_W1T;
    int c0 = blockIdx.x * 32;
    int k0 = blockIdx.y * 32;
    int tx = threadIdx.x, ty = threadIdx.y;
    sm[ty][tx] = src[(size_t)(k0 + ty) * Cdim + c0 + tx];
    __syncthreads();
    int n = nOff + nMul * (c0 + ty);
    dst[(size_t)n * 1024 + k0 + tx] = f2tf(sm[tx][ty]);
}

__global__ void pack_bias_kernel(const float* __restrict__ bzf, const float* __restrict__ bhf,
                                 const float* __restrict__ bzs, const float* __restrict__ bhs) {
    int n = blockIdx.x * 256 + threadIdx.x;
    if (n >= N1) return;
    int c = n >> 1, hp = n & 1;
    float v;
    if (c < 512) v = hp ? bhf[c]       : bzf[c];
    else         v = hp ? bhs[c - 512] : bzs[c - 512];
    g_b1[n] = v;
}

// ---------------- tf32 mma.sync GEMM: 128x128 CTA, BK=16, 4 warps (64x64 each) ----------------
// R3 layout: tiles [s][col], s = k-within-chunk (0..15), stride 136 words,
// element (m, s) at col = m ^ ((s & 12) << 1). Conflict-free stores + fragment loads.
#define SSTRIDE 136

template <int MODE>   // 1 = GEMM1 (scan-coeff epilogue), 2 = GEMM2 (gated-output epilogue)
__device__ __forceinline__ void gemm_core(const float* __restrict__ A,
                                          const uint32_t* __restrict__ BT,
                                          const float* __restrict__ bias,
                                          float* __restrict__ Out) {
    __shared__ uint32_t As[2][16][SSTRIDE];
    __shared__ uint32_t Bs[2][16][SSTRIDE];

    const int tid  = threadIdx.x;
    const int lane = tid & 31, w = tid >> 5;
    const int g = lane >> 2, t = lane & 3;
    const int wm = (w & 1) * 64, wn = (w >> 1) * 64;
    const int bm = blockIdx.y * 128, bn = blockIdx.x * 128;
    const int mrow = tid >> 2;     // 0..31, +32*i
    const int kq   = tid & 3;      // k-quad

    const float*    Ag = A  + (size_t)bm * 1024 + kq * 4;
    const uint32_t* Bg = BT + (size_t)bn * 1024 + kq * 4;

    float acc[4][8][4];
#pragma unroll
    for (int i = 0; i < 4; i++)
#pragma unroll
        for (int j = 0; j < 8; j++)
#pragma unroll
            for (int q = 0; q < 4; q++) acc[i][j][q] = 0.0f;

    uint32_t avA[4][4];   // staged A, already tf32 bits
    uint4    avB[4];      // staged B (already tf32 bits in gmem)

#pragma unroll
    for (int i = 0; i < 4; i++) {
        int m = mrow + 32 * i;
        float4 av = *(const float4*)(Ag + (size_t)m * 1024);
        avA[i][0] = f2tf(av.x); avA[i][1] = f2tf(av.y);
        avA[i][2] = f2tf(av.z); avA[i][3] = f2tf(av.w);
        avB[i] = *(const uint4*)(Bg + (size_t)m * 1024);
    }

    for (int kt = 0; kt < 64; kt++) {
        int p = kt & 1;
        // store staged regs into smem (transposed + swizzled)
#pragma unroll
        for (int i = 0; i < 4; i++) {
            int m = mrow + 32 * i;
            int col = m ^ (kq << 3);
            As[p][kq * 4 + 0][col] = avA[i][0];
            As[p][kq * 4 + 1][col] = avA[i][1];
            As[p][kq * 4 + 2][col] = avA[i][2];
            As[p][kq * 4 + 3][col] = avA[i][3];
            Bs[p][kq * 4 + 0][col] = avB[i].x;
            Bs[p][kq * 4 + 1][col] = avB[i].y;
            Bs[p][kq * 4 + 2][col] = avB[i].z;
            Bs[p][kq * 4 + 3][col] = avB[i].w;
        }
        __syncthreads();
        if (kt < 63) {
#pragma unroll
            for (int i = 0; i < 4; i++) {
                int m = mrow + 32 * i;
                float4 av = *(const float4*)(Ag + (size_t)m * 1024 + (kt + 1) * 16);
                avA[i][0] = f2tf(av.x); avA[i][1] = f2tf(av.y);
                avA[i][2] = f2tf(av.z); avA[i][3] = f2tf(av.w);
                avB[i] = *(const uint4*)(Bg + (size_t)m * 1024 + (kt + 1) * 16);
            }
        }
        // compute on buffer p: pure LDS + HMMA (no cvt)
#pragma unroll
        for (int kk = 0; kk < 16; kk += 8) {
            const int X0 = kk * 2;       // xor const for s in [kk, kk+4)
            const int X1 = kk * 2 + 8;   // xor const for s in [kk+4, kk+8)
            uint32_t bf[8][2];
#pragma unroll
            for (int nt = 0; nt < 8; nt++) {
                int n = wn + nt * 8 + g;
                bf[nt][0] = Bs[p][kk + t][n ^ X0];
                bf[nt][1] = Bs[p][kk + t + 4][n ^ X1];
            }
#pragma unroll
            for (int mt = 0; mt < 4; mt++) {
                int m = wm + mt * 16 + g;
                uint32_t a0 = As[p][kk + t][m ^ X0];
                uint32_t a1 = As[p][kk + t][(m + 8) ^ X0];
                uint32_t a2 = As[p][kk + t + 4][m ^ X1];
                uint32_t a3 = As[p][kk + t + 4][(m + 8) ^ X1];
#pragma unroll
                for (int nt = 0; nt < 8; nt++)
                    mma_tf32(acc[mt][nt], a0, a1, a2, a3, bf[nt][0], bf[nt][1]);
            }
        }
        __syncthreads();
    }

    // ---------------- epilogue ----------------
    const int NOUT = (MODE == 1) ? N1 : NC;
#pragma unroll
    for (int mt = 0; mt < 4; mt++) {
#pragma unroll
        for (int nt = 0; nt < 8; nt++) {
            int row = bm + wm + mt * 16 + g;
            int col = bn + wn + nt * 8 + t * 2;       // even: one (z, h~) pair
            float2 bb = *(const float2*)&bias[col];
            const float* a4 = acc[mt][nt];
            if (MODE == 1) {
                float z0 = sigmoidf_(a4[0] + bb.x);
                float h0 = a4[1] + bb.y;
                *(float2*)&Out[(size_t)row * NOUT + col] = make_float2(1.0f - z0, z0 * h0);
                float z1 = sigmoidf_(a4[2] + bb.x);
                float h1 = a4[3] + bb.y;
                *(float2*)&Out[(size_t)(row + 8) * NOUT + col] = make_float2(1.0f - z1, z1 * h1);
            } else {
                float2 hv0 = *(const float2*)&g_h[(size_t)row * NC + col];
                *(float2*)&Out[(size_t)row * NOUT + col] =
                    make_float2(hv0.x * sigmoidf_(a4[0] + bb.x),
                                hv0.y * sigmoidf_(a4[1] + bb.y));
                float2 hv1 = *(const float2*)&g_h[(size_t)(row + 8) * NC + col];
                *(float2*)&Out[(size_t)(row + 8) * NOUT + col] =
                    make_float2(hv1.x * sigmoidf_(a4[2] + bb.x),
                                hv1.y * sigmoidf_(a4[3] + bb.y));
            }
        }
    }
}

__global__ __launch_bounds__(128) void gemm1_mma(const float* __restrict__ x) {
    gemm_core<1>(x, g_W1T, g_b1, g_Y);
}
__global__ __launch_bounds__(128) void gemm2_mma(const float* __restrict__ bg,
                                                 float* __restrict__ out) {
    gemm_core<2>(g_h, g_WgT, bg, out);
}

// ---------------- scan (3-phase chunked) ----------------
__global__ __launch_bounds__(256) void scan_phase1() {
    int lane = blockIdx.x * blockDim.x + threadIdx.x;
    int j    = blockIdx.y;
    int b    = lane >> 10;
    int c    = lane & (NC - 1);
    const float2* Y2 = (const float2*)g_Y;
    size_t base = ((size_t)(b * S_ + j * LC)) * NC + c;
    float A = 1.0f, H = 0.0f;
#pragma unroll 8
    for (int t = 0; t < LC; t++) {
        float2 ab = Y2[base + (size_t)t * NC];
        A *= ab.x;
        H = fmaf(ab.x, H, ab.y);
    }
    g_Agg[j * LANES + lane] = make_float2(A, H);
}

__global__ __launch_bounds__(256) void scan_phase2() {
    int lane = blockIdx.x * blockDim.x + threadIdx.x;
    float carry = 0.0f;
#pragma unroll
    for (int j = 0; j < NCHUNK; j++) {
        float2 e = g_Agg[j * LANES + lane];
        g_Carry[j * LANES + lane] = carry;
        carry = fmaf(e.x, carry, e.y);
    }
}

__global__ __launch_bounds__(256) void scan_phase3() {
    int lane = blockIdx.x * blockDim.x + threadIdx.x;
    int j    = blockIdx.y;
    int b    = lane >> 10;
    int c    = lane & (NC - 1);
    const float2* Y2 = (const float2*)g_Y;
    size_t m0 = (size_t)(b * S_ + j * LC);
    size_t base = m0 * NC + c;
    float H = g_Carry[j * LANES + lane];
#pragma unroll 8
    for (int t = 0; t < LC; t++) {
        float2 ab = Y2[base + (size_t)t * NC];
        H = fmaf(ab.x, H, ab.y);
        g_h[(m0 + t) * NC + c] = H;
    }
}

// ---------------- launch ----------------
// Order chosen so gemm1_mma is the 6th launch: ncu's `-s 5 -c 1` then captures
// the GEMM (the actual hot kernel) instead of a pack kernel.
extern "C" void kernel_launch(void* const* d_in, const int* in_sizes, int n_in,
                              void* d_out, int out_size) {
    const float* x   = (const float*)d_in[0];
    const float* Wzf = (const float*)d_in[1];
    const float* bzf = (const float*)d_in[2];
    const float* Whf = (const float*)d_in[3];
    const float* bhf = (const float*)d_in[4];
    const float* Wzs = (const float*)d_in[5];
    const float* bzs = (const float*)d_in[6];
    const float* Whs = (const float*)d_in[7];
    const float* bhs = (const float*)d_in[8];
    const float* Wg  = (const float*)d_in[9];
    const float* bg  = (const float*)d_in[10];
    float* out = (float*)d_out;

    dim3 tb(32, 32);
    // 5 launches before gemm1 (indices 0..4), gemm1 at index 5
    transpose_pack_kernel<<<dim3(16, 32), tb>>>(Wzf, 512, 2, 0, 0);
    transpose_pack_kernel<<<dim3(16, 32), tb>>>(Whf, 512, 2, 1, 0);
    transpose_pack_kernel<<<dim3(16, 32), tb>>>(Wzs, 512, 2, 1024, 0);
    transpose_pack_kernel<<<dim3(16, 32), tb>>>(Whs, 512, 2, 1025, 0);
    pack_bias_kernel<<<N1 / 256, 256>>>(bzf, bhf, bzs, bhs);

    gemm1_mma<<<dim3(N1 / 128, M_ / 128), 128>>>(x);

    transpose_pack_kernel<<<dim3(32, 32), tb>>>(Wg, 1024, 1, 0, 1);  // only needed by gemm2

    scan_phase1<<<dim3(LANES / 256, NCHUNK), 256>>>();
    scan_phase2<<<LANES / 256, 256>>>();
    scan_phase3<<<dim3(LANES / 256, NCHUNK), 256>>>();

    gemm2_mma<<<dim3(NC / 128, M_ / 128), 128>>>(bg, out);
}

// round 6
// speedup vs baseline: 1.4182x; 1.4068x over previous
#include <cuda_runtime.h>
#include <cuda_fp16.h>
#include <cstdint>
#include <math.h>

// Problem constants
#define B_      4
#define S_      4096
#define DIN     1024
#define NC      1024
#define N1      2048
#define M_      (B_*S_)         // 16384
#define LANES   (B_*NC)         // 4096
#define NCHUNK  64
#define LC      (S_/NCHUNK)     // 64
#define KP      512             // k-pairs per row (1024 k / 2)

// ---------------- scratch (static device globals) ----------------
__device__ uint32_t g_W1T[(size_t)N1 * KP];       // packed weights [n][kpair], half2
__device__ uint32_t g_WgT[(size_t)NC * KP];       // gate weights [n][kpair], half2
__device__ float    g_b1[N1];
__device__ float    g_Y[(size_t)M_ * N1];         // interleaved (a,b) pairs for the scan
__device__ float    g_h[(size_t)M_ * NC];
__device__ float2   g_Agg[NCHUNK * LANES];
__device__ float    g_Carry[NCHUNK * LANES];

__device__ __forceinline__ float sigmoidf_(float x) { return 1.0f / (1.0f + __expf(-x)); }
__device__ __forceinline__ uint32_t packh2(float lo, float hi) {
    __half2 h = __floats2half2_rn(lo, hi);     // lo -> low half (lower k)
    return *(uint32_t*)&h;
}

__device__ __forceinline__ void mma_f16(float c[4],
                                        uint32_t a0, uint32_t a1, uint32_t a2, uint32_t a3,
                                        uint32_t b0, uint32_t b1) {
    asm volatile(
        "mma.sync.aligned.m16n8k16.row.col.f32.f16.f16.f32 "
        "{%0,%1,%2,%3}, {%4,%5,%6,%7}, {%8,%9}, {%0,%1,%2,%3};"
        : "+f"(c[0]), "+f"(c[1]), "+f"(c[2]), "+f"(c[3])
        : "r"(a0), "r"(a1), "r"(a2), "r"(a3), "r"(b0), "r"(b1));
}

// ---------------- weight transpose / pack (emits half2 k-pairs) ----------------
// which==0: dst=g_W1T ; which==1: dst=g_WgT
// dst[(nOff + nMul*c) * 512 + kpair] = half2(src[2kp][c], src[2kp+1][c])
__global__ void transpose_pack_kernel(const float* __restrict__ src,
                                      int Cdim, int nMul, int nOff, int which) {
    __shared__ float sm[32][33];
    uint32_t* dst = which ? g_WgT : g_W1T;
    int c0 = blockIdx.x * 32;
    int k0 = blockIdx.y * 32;
    int tx = threadIdx.x, ty = threadIdx.y;
    sm[tx][ty] = src[(size_t)(k0 + tx) * Cdim + c0 + ty];   // sm[k][c]
    __syncthreads();
    if (tx < 16) {
        int n = nOff + nMul * (c0 + ty);
        dst[(size_t)n * KP + (k0 >> 1) + tx] = packh2(sm[2 * tx][ty], sm[2 * tx + 1][ty]);
    }
}

__global__ void pack_bias_kernel(const float* __restrict__ bzf, const float* __restrict__ bhf,
                                 const float* __restrict__ bzs, const float* __restrict__ bhs) {
    int n = blockIdx.x * 256 + threadIdx.x;
    if (n >= N1) return;
    int c = n >> 1, hp = n & 1;
    float v;
    if (c < 512) v = hp ? bhf[c]       : bzf[c];
    else         v = hp ? bhs[c - 512] : bzs[c - 512];
    g_b1[n] = v;
}

// ---------------- fp16 mma.sync GEMM: 128x128 CTA, BK=32, 4 warps (64x64 each) ----------------
// Tile layout identical to R3, with row index s = k-pair within chunk (0..15):
// element (m, s) at col = m ^ ((s & 12) << 1), stride 136 u32. Conflict-free.
#define SSTRIDE 136

template <int MODE>   // 1 = GEMM1 (scan-coeff epilogue), 2 = GEMM2 (gated-output epilogue)
__device__ __forceinline__ void gemm_core(const float* __restrict__ A,
                                          const uint32_t* __restrict__ BT,
                                          const float* __restrict__ bias,
                                          float* __restrict__ Out) {
    __shared__ uint32_t As[2][16][SSTRIDE];
    __shared__ uint32_t Bs[2][16][SSTRIDE];

    const int tid  = threadIdx.x;
    const int lane = tid & 31, w = tid >> 5;
    const int g = lane >> 2, t = lane & 3;
    const int wm = (w & 1) * 64, wn = (w >> 1) * 64;
    const int bm = blockIdx.y * 128, bn = blockIdx.x * 128;
    const int mrow = tid >> 2;     // 0..31, +32*i
    const int kq   = tid & 3;      // quad within chunk

    const float*    Ag = A  + (size_t)bm * 1024 + kq * 4;   // fp32 activations
    const uint32_t* Bg = BT + (size_t)bn * KP   + kq * 4;   // half2 weights (kpair units)

    float acc[4][8][4];
#pragma unroll
    for (int i = 0; i < 4; i++)
#pragma unroll
        for (int j = 0; j < 8; j++)
#pragma unroll
            for (int q = 0; q < 4; q++) acc[i][j][q] = 0.0f;

    uint32_t stA[4][4];   // staged A half2: kpairs kq*2, kq*2+1, kq*2+8, kq*2+9
    uint4    stB[4];      // staged B half2: kpairs kq*4 .. kq*4+3

    // prologue: load + convert chunk 0
#pragma unroll
    for (int i = 0; i < 4; i++) {
        int m = mrow + 32 * i;
        float4 fa = *(const float4*)(Ag + (size_t)m * 1024);
        float4 fb = *(const float4*)(Ag + (size_t)m * 1024 + 16);
        stA[i][0] = packh2(fa.x, fa.y);
        stA[i][1] = packh2(fa.z, fa.w);
        stA[i][2] = packh2(fb.x, fb.y);
        stA[i][3] = packh2(fb.z, fb.w);
        stB[i] = *(const uint4*)(Bg + (size_t)m * KP);
    }

    for (int kt = 0; kt < 32; kt++) {
        int p = kt & 1;
        // store staged chunk into buffer p (transposed + swizzled)
#pragma unroll
        for (int i = 0; i < 4; i++) {
            int m = mrow + 32 * i;
            {   // A: kpairs s = kq*2, kq*2+1, kq*2+8, kq*2+9
                int s0 = kq * 2, s1 = kq * 2 + 1, s2 = kq * 2 + 8, s3 = kq * 2 + 9;
                As[p][s0][m ^ ((s0 & 12) << 1)] = stA[i][0];
                As[p][s1][m ^ ((s1 & 12) << 1)] = stA[i][1];
                As[p][s2][m ^ ((s2 & 12) << 1)] = stA[i][2];
                As[p][s3][m ^ ((s3 & 12) << 1)] = stA[i][3];
            }
            {   // B: kpairs s = kq*4 .. kq*4+3
                int s0 = kq * 4, s1 = kq * 4 + 1, s2 = kq * 4 + 2, s3 = kq * 4 + 3;
                Bs[p][s0][m ^ ((s0 & 12) << 1)] = stB[i].x;
                Bs[p][s1][m ^ ((s1 & 12) << 1)] = stB[i].y;
                Bs[p][s2][m ^ ((s2 & 12) << 1)] = stB[i].z;
                Bs[p][s3][m ^ ((s3 & 12) << 1)] = stB[i].w;
            }
        }
        __syncthreads();
        // prefetch + convert next chunk
        if (kt < 31) {
#pragma unroll
            for (int i = 0; i < 4; i++) {
                int m = mrow + 32 * i;
                float4 fa = *(const float4*)(Ag + (size_t)m * 1024 + (kt + 1) * 32);
                float4 fb = *(const float4*)(Ag + (size_t)m * 1024 + (kt + 1) * 32 + 16);
                stA[i][0] = packh2(fa.x, fa.y);
                stA[i][1] = packh2(fa.z, fa.w);
                stA[i][2] = packh2(fb.x, fb.y);
                stA[i][3] = packh2(fb.z, fb.w);
                stB[i] = *(const uint4*)(Bg + (size_t)m * KP + (kt + 1) * 16);
            }
        }
        // compute on buffer p: two k16 steps (kpair bases sb = 0, 8)
#pragma unroll
        for (int sb = 0; sb < 16; sb += 8) {
            const int X0 = sb * 2;       // swizzle const for s in [sb, sb+4)
            const int X1 = sb * 2 + 8;   // for s in [sb+4, sb+8)
            uint32_t bf[8][2];
#pragma unroll
            for (int nt = 0; nt < 8; nt++) {
                int n = wn + nt * 8 + g;
                bf[nt][0] = Bs[p][sb + t][n ^ X0];
                bf[nt][1] = Bs[p][sb + t + 4][n ^ X1];
            }
#pragma unroll
            for (int mt = 0; mt < 4; mt++) {
                int m = wm + mt * 16 + g;
                uint32_t a0 = As[p][sb + t][m ^ X0];
                uint32_t a1 = As[p][sb + t][(m + 8) ^ X0];
                uint32_t a2 = As[p][sb + t + 4][m ^ X1];
                uint32_t a3 = As[p][sb + t + 4][(m + 8) ^ X1];
#pragma unroll
                for (int nt = 0; nt < 8; nt++)
                    mma_f16(acc[mt][nt], a0, a1, a2, a3, bf[nt][0], bf[nt][1]);
            }
        }
        __syncthreads();
    }

    // ---------------- epilogue (C fragment layout identical to tf32 case) ----------------
    const int NOUT = (MODE == 1) ? N1 : NC;
#pragma unroll
    for (int mt = 0; mt < 4; mt++) {
#pragma unroll
        for (int nt = 0; nt < 8; nt++) {
            int row = bm + wm + mt * 16 + g;
            int col = bn + wn + nt * 8 + t * 2;       // even: one (z, h~) pair
            float2 bb = *(const float2*)&bias[col];
            const float* a4 = acc[mt][nt];
            if (MODE == 1) {
                float z0 = sigmoidf_(a4[0] + bb.x);
                float h0 = a4[1] + bb.y;
                *(float2*)&Out[(size_t)row * NOUT + col] = make_float2(1.0f - z0, z0 * h0);
                float z1 = sigmoidf_(a4[2] + bb.x);
                float h1 = a4[3] + bb.y;
                *(float2*)&Out[(size_t)(row + 8) * NOUT + col] = make_float2(1.0f - z1, z1 * h1);
            } else {
                float2 hv0 = *(const float2*)&g_h[(size_t)row * NC + col];
                *(float2*)&Out[(size_t)row * NOUT + col] =
                    make_float2(hv0.x * sigmoidf_(a4[0] + bb.x),
                                hv0.y * sigmoidf_(a4[1] + bb.y));
                float2 hv1 = *(const float2*)&g_h[(size_t)(row + 8) * NC + col];
                *(float2*)&Out[(size_t)(row + 8) * NOUT + col] =
                    make_float2(hv1.x * sigmoidf_(a4[2] + bb.x),
                                hv1.y * sigmoidf_(a4[3] + bb.y));
            }
        }
    }
}

__global__ __launch_bounds__(128) void gemm1_mma(const float* __restrict__ x) {
    gemm_core<1>(x, g_W1T, g_b1, g_Y);
}
__global__ __launch_bounds__(128) void gemm2_mma(const float* __restrict__ bg,
                                                 float* __restrict__ out) {
    gemm_core<2>(g_h, g_WgT, bg, out);
}

// ---------------- scan (3-phase chunked) ----------------
__global__ __launch_bounds__(256) void scan_phase1() {
    int lane = blockIdx.x * blockDim.x + threadIdx.x;
    int j    = blockIdx.y;
    int b    = lane >> 10;
    int c    = lane & (NC - 1);
    const float2* Y2 = (const float2*)g_Y;
    size_t base = ((size_t)(b * S_ + j * LC)) * NC + c;
    float A = 1.0f, H = 0.0f;
#pragma unroll 8
    for (int t = 0; t < LC; t++) {
        float2 ab = Y2[base + (size_t)t * NC];
        A *= ab.x;
        H = fmaf(ab.x, H, ab.y);
    }
    g_Agg[j * LANES + lane] = make_float2(A, H);
}

__global__ __launch_bounds__(256) void scan_phase2() {
    int lane = blockIdx.x * blockDim.x + threadIdx.x;
    float carry = 0.0f;
#pragma unroll
    for (int j = 0; j < NCHUNK; j++) {
        float2 e = g_Agg[j * LANES + lane];
        g_Carry[j * LANES + lane] = carry;
        carry = fmaf(e.x, carry, e.y);
    }
}

__global__ __launch_bounds__(256) void scan_phase3() {
    int lane = blockIdx.x * blockDim.x + threadIdx.x;
    int j    = blockIdx.y;
    int b    = lane >> 10;
    int c    = lane & (NC - 1);
    const float2* Y2 = (const float2*)g_Y;
    size_t m0 = (size_t)(b * S_ + j * LC);
    size_t base = m0 * NC + c;
    float H = g_Carry[j * LANES + lane];
#pragma unroll 8
    for (int t = 0; t < LC; t++) {
        float2 ab = Y2[base + (size_t)t * NC];
        H = fmaf(ab.x, H, ab.y);
        g_h[(m0 + t) * NC + c] = H;
    }
}

// ---------------- launch ----------------
// gemm1_mma is the 6th launch so ncu's `-s 5 -c 1` captures it.
extern "C" void kernel_launch(void* const* d_in, const int* in_sizes, int n_in,
                              void* d_out, int out_size) {
    const float* x   = (const float*)d_in[0];
    const float* Wzf = (const float*)d_in[1];
    const float* bzf = (const float*)d_in[2];
    const float* Whf = (const float*)d_in[3];
    const float* bhf = (const float*)d_in[4];
    const float* Wzs = (const float*)d_in[5];
    const float* bzs = (const float*)d_in[6];
    const float* Whs = (const float*)d_in[7];
    const float* bhs = (const float*)d_in[8];
    const float* Wg  = (const float*)d_in[9];
    const float* bg  = (const float*)d_in[10];
    float* out = (float*)d_out;

    dim3 tb(32, 32);
    transpose_pack_kernel<<<dim3(16, 32), tb>>>(Wzf, 512, 2, 0, 0);
    transpose_pack_kernel<<<dim3(16, 32), tb>>>(Whf, 512, 2, 1, 0);
    transpose_pack_kernel<<<dim3(16, 32), tb>>>(Wzs, 512, 2, 1024, 0);
    transpose_pack_kernel<<<dim3(16, 32), tb>>>(Whs, 512, 2, 1025, 0);
    pack_bias_kernel<<<N1 / 256, 256>>>(bzf, bhf, bzs, bhs);

    gemm1_mma<<<dim3(N1 / 128, M_ / 128), 128>>>(x);

    transpose_pack_kernel<<<dim3(32, 32), tb>>>(Wg, 1024, 1, 0, 1);

    scan_phase1<<<dim3(LANES / 256, NCHUNK), 256>>>();
    scan_phase2<<<LANES / 256, 256>>>();
    scan_phase3<<<dim3(LANES / 256, NCHUNK), 256>>>();

    gemm2_mma<<<dim3(NC / 128, M_ / 128), 128>>>(bg, out);
}

// round 7
// speedup vs baseline: 1.4894x; 1.0502x over previous
#include <cuda_runtime.h>
#include <cuda_fp16.h>
#include <cstdint>
#include <math.h>

// Problem constants
#define B_      4
#define S_      4096
#define DIN     1024
#define NC      1024
#define N1      2048
#define M_      (B_*S_)         // 16384
#define LANES   (B_*NC)         // 4096
#define NCHUNK  64
#define LC      (S_/NCHUNK)     // 64
#define KP      512             // k-pairs per row (1024 k / 2)

// ---------------- scratch (static device globals) ----------------
__device__ uint32_t g_W1T[(size_t)N1 * KP];       // packed weights [n][k] halves (u32 = kpair)
__device__ uint32_t g_WgT[(size_t)NC * KP];       // gate weights [n][k] halves
__device__ float    g_b1[N1];
__device__ float    g_Y[(size_t)M_ * N1];         // interleaved (a,b) pairs for the scan
__device__ float    g_h[(size_t)M_ * NC];
__device__ float2   g_Agg[NCHUNK * LANES];
__device__ float    g_Carry[NCHUNK * LANES];

__device__ __forceinline__ float sigmoidf_(float x) { return 1.0f / (1.0f + __expf(-x)); }
__device__ __forceinline__ uint32_t packh2(float lo, float hi) {
    __half2 h = __floats2half2_rn(lo, hi);
    return *(uint32_t*)&h;
}
__device__ __forceinline__ uint32_t smem_u32(const void* p) {
    uint32_t a;
    asm("{ .reg .u64 t; cvta.to.shared.u64 t, %1; cvt.u32.u64 %0, t; }" : "=r"(a) : "l"(p));
    return a;
}
__device__ __forceinline__ void ldsm_x4(uint32_t r[4], uint32_t addr) {
    asm volatile("ldmatrix.sync.aligned.m8n8.x4.shared.b16 {%0,%1,%2,%3}, [%4];"
                 : "=r"(r[0]), "=r"(r[1]), "=r"(r[2]), "=r"(r[3]) : "r"(addr));
}
__device__ __forceinline__ void mma_f16(float c[4],
                                        uint32_t a0, uint32_t a1, uint32_t a2, uint32_t a3,
                                        uint32_t b0, uint32_t b1) {
    asm volatile(
        "mma.sync.aligned.m16n8k16.row.col.f32.f16.f16.f32 "
        "{%0,%1,%2,%3}, {%4,%5,%6,%7}, {%8,%9}, {%0,%1,%2,%3};"
        : "+f"(c[0]), "+f"(c[1]), "+f"(c[2]), "+f"(c[3])
        : "r"(a0), "r"(a1), "r"(a2), "r"(a3), "r"(b0), "r"(b1));
}

// ---------------- weight transpose / pack (emits half2 k-pairs) ----------------
__global__ void transpose_pack_kernel(const float* __restrict__ src,
                                      int Cdim, int nMul, int nOff, int which) {
    __shared__ float sm[32][33];
    uint32_t* dst = which ? g_WgT : g_W1T;
    int c0 = blockIdx.x * 32;
    int k0 = blockIdx.y * 32;
    int tx = threadIdx.x, ty = threadIdx.y;
    sm[tx][ty] = src[(size_t)(k0 + tx) * Cdim + c0 + ty];   // sm[k][c]
    __syncthreads();
    if (tx < 16) {
        int n = nOff + nMul * (c0 + ty);
        dst[(size_t)n * KP + (k0 >> 1) + tx] = packh2(sm[2 * tx][ty], sm[2 * tx + 1][ty]);
    }
}

__global__ void pack_bias_kernel(const float* __restrict__ bzf, const float* __restrict__ bhf,
                                 const float* __restrict__ bzs, const float* __restrict__ bhs) {
    int n = blockIdx.x * 256 + threadIdx.x;
    if (n >= N1) return;
    int c = n >> 1, hp = n & 1;
    float v;
    if (c < 512) v = hp ? bhf[c]       : bzf[c];
    else         v = hp ? bhs[c - 512] : bzs[c - 512];
    g_b1[n] = v;
}

// ---------------- fp16 GEMM with ldmatrix: 128x128 CTA, BK=32, 4 warps (64x64 each) -------
// SMEM: [row][32 halves] = 64 B/row; 16B chunk swizzle: phys_chunk = chunk ^ ((row>>1)&3).
// Verified conflict-free for ldmatrix 8-row tiles and the STS.128 store pattern.

template <int MODE>   // 1 = GEMM1 (scan-coeff epilogue), 2 = GEMM2 (gated-output epilogue)
__device__ __forceinline__ void gemm_core(const float* __restrict__ A,
                                          const uint32_t* __restrict__ BT,
                                          const float* __restrict__ bias,
                                          float* __restrict__ Out) {
    __shared__ __align__(16) uint8_t sA[2][8192];
    __shared__ __align__(16) uint8_t sB[2][8192];

    const int tid  = threadIdx.x;
    const int lane = tid & 31, w = tid >> 5;
    const int g = lane >> 2, t = lane & 3;
    const int wm = (w & 1) * 64, wn = (w >> 1) * 64;
    const int bm = blockIdx.y * 128, bn = blockIdx.x * 128;
    const int mrow = tid >> 2;     // 0..31 (+32*i)
    const int kq   = tid & 3;      // 16B chunk within the 64B row-stage

    const float*    Ag = A  + (size_t)bm * 1024;
    const uint32_t* Bg = BT + (size_t)bn * KP;

    // store-side precompute: swizzled chunk byte offset (same for all i since 32*i
    // doesn't touch bits 1..2 of m)
    const int sm_st  = (mrow >> 1) & 3;
    const int stChunk = ((kq ^ sm_st) << 4);

    // ldmatrix-side precompute
    const int ro = lane & 15, hi = lane >> 4;
    uint32_t uA0 = smem_u32(sA[0]), uB0 = smem_u32(sB[0]);
    int rbA[4], sxA[4], rbB[4], sxB[4];
#pragma unroll
    for (int q = 0; q < 4; q++) {
        int rowA = wm + q * 16 + ro;
        rbA[q] = rowA * 64; sxA[q] = (rowA >> 1) & 3;
        int rowB = wn + q * 16 + ro;
        rbB[q] = rowB * 64; sxB[q] = (rowB >> 1) & 3;
    }

    float acc[4][8][4];
#pragma unroll
    for (int i = 0; i < 4; i++)
#pragma unroll
        for (int j = 0; j < 8; j++)
#pragma unroll
            for (int q = 0; q < 4; q++) acc[i][j][q] = 0.0f;

    uint4 stA[4], stB[4];

    // prologue: load + convert chunk 0
#pragma unroll
    for (int i = 0; i < 4; i++) {
        int m = mrow + 32 * i;
        float4 fa = *(const float4*)(Ag + (size_t)m * 1024 + kq * 8);
        float4 fb = *(const float4*)(Ag + (size_t)m * 1024 + kq * 8 + 4);
        stA[i] = make_uint4(packh2(fa.x, fa.y), packh2(fa.z, fa.w),
                            packh2(fb.x, fb.y), packh2(fb.z, fb.w));
        stB[i] = *(const uint4*)(Bg + (size_t)m * KP + kq * 4);
    }

    for (int kt = 0; kt < 32; kt++) {
        const int p = kt & 1;
        // store staged chunk into buffer p (swizzled STS.128)
#pragma unroll
        for (int i = 0; i < 4; i++) {
            int m = mrow + 32 * i;
            *(uint4*)(&sA[p][m * 64 + stChunk]) = stA[i];
            *(uint4*)(&sB[p][m * 64 + stChunk]) = stB[i];
        }
        __syncthreads();
        // prefetch + convert next chunk
        if (kt < 31) {
            const int kof = (kt + 1) * 32 + kq * 8;
#pragma unroll
            for (int i = 0; i < 4; i++) {
                int m = mrow + 32 * i;
                float4 fa = *(const float4*)(Ag + (size_t)m * 1024 + kof);
                float4 fb = *(const float4*)(Ag + (size_t)m * 1024 + kof + 4);
                stA[i] = make_uint4(packh2(fa.x, fa.y), packh2(fa.z, fa.w),
                                    packh2(fb.x, fb.y), packh2(fb.z, fb.w));
                stB[i] = *(const uint4*)(Bg + (size_t)m * KP + (kt + 1) * 16 + kq * 4);
            }
        }
        // compute on buffer p: 2 x k16 steps, ldmatrix + HMMA only
        uint32_t baseA = uA0 + p * 8192, baseB = uB0 + p * 8192;
#pragma unroll
        for (int sb = 0; sb < 2; sb++) {
            const int ch = sb * 2 + hi;
            uint32_t af[4][4], bf[4][4];
#pragma unroll
            for (int q = 0; q < 4; q++)
                ldsm_x4(af[q], baseA + rbA[q] + ((ch ^ sxA[q]) << 4));
#pragma unroll
            for (int q = 0; q < 4; q++)
                ldsm_x4(bf[q], baseB + rbB[q] + ((ch ^ sxB[q]) << 4));
#pragma unroll
            for (int mt = 0; mt < 4; mt++)
#pragma unroll
                for (int nt = 0; nt < 8; nt++) {
                    int np = nt >> 1, q = nt & 1;
                    mma_f16(acc[mt][nt], af[mt][0], af[mt][1], af[mt][2], af[mt][3],
                            bf[np][q], bf[np][2 + q]);
                }
        }
        __syncthreads();
    }

    // ---------------- epilogue (fragment layout unchanged) ----------------
    const int NOUT = (MODE == 1) ? N1 : NC;
#pragma unroll
    for (int mt = 0; mt < 4; mt++) {
#pragma unroll
        for (int nt = 0; nt < 8; nt++) {
            int row = bm + wm + mt * 16 + g;
            int col = bn + wn + nt * 8 + t * 2;       // even: one (z, h~) pair
            float2 bb = *(const float2*)&bias[col];
            const float* a4 = acc[mt][nt];
            if (MODE == 1) {
                float z0 = sigmoidf_(a4[0] + bb.x);
                float h0 = a4[1] + bb.y;
                *(float2*)&Out[(size_t)row * NOUT + col] = make_float2(1.0f - z0, z0 * h0);
                float z1 = sigmoidf_(a4[2] + bb.x);
                float h1 = a4[3] + bb.y;
                *(float2*)&Out[(size_t)(row + 8) * NOUT + col] = make_float2(1.0f - z1, z1 * h1);
            } else {
                float2 hv0 = *(const float2*)&g_h[(size_t)row * NC + col];
                *(float2*)&Out[(size_t)row * NOUT + col] =
                    make_float2(hv0.x * sigmoidf_(a4[0] + bb.x),
                                hv0.y * sigmoidf_(a4[1] + bb.y));
                float2 hv1 = *(const float2*)&g_h[(size_t)(row + 8) * NC + col];
                *(float2*)&Out[(size_t)(row + 8) * NOUT + col] =
                    make_float2(hv1.x * sigmoidf_(a4[2] + bb.x),
                                hv1.y * sigmoidf_(a4[3] + bb.y));
            }
        }
    }
}

__global__ __launch_bounds__(128) void gemm1_mma(const float* __restrict__ x) {
    gemm_core<1>(x, g_W1T, g_b1, g_Y);
}
__global__ __launch_bounds__(128) void gemm2_mma(const float* __restrict__ bg,
                                                 float* __restrict__ out) {
    gemm_core<2>(g_h, g_WgT, bg, out);
}

// ---------------- scan (3-phase chunked) ----------------
__global__ __launch_bounds__(256) void scan_phase1() {
    int lane = blockIdx.x * blockDim.x + threadIdx.x;
    int j    = blockIdx.y;
    int b    = lane >> 10;
    int c    = lane & (NC - 1);
    const float2* Y2 = (const float2*)g_Y;
    size_t base = ((size_t)(b * S_ + j * LC)) * NC + c;
    float A = 1.0f, H = 0.0f;
#pragma unroll 8
    for (int t = 0; t < LC; t++) {
        float2 ab = Y2[base + (size_t)t * NC];
        A *= ab.x;
        H = fmaf(ab.x, H, ab.y);
    }
    g_Agg[j * LANES + lane] = make_float2(A, H);
}

__global__ __launch_bounds__(256) void scan_phase2() {
    int lane = blockIdx.x * blockDim.x + threadIdx.x;
    float carry = 0.0f;
#pragma unroll
    for (int j = 0; j < NCHUNK; j++) {
        float2 e = g_Agg[j * LANES + lane];
        g_Carry[j * LANES + lane] = carry;
        carry = fmaf(e.x, carry, e.y);
    }
}

__global__ __launch_bounds__(256) void scan_phase3() {
    int lane = blockIdx.x * blockDim.x + threadIdx.x;
    int j    = blockIdx.y;
    int b    = lane >> 10;
    int c    = lane & (NC - 1);
    const float2* Y2 = (const float2*)g_Y;
    size_t m0 = (size_t)(b * S_ + j * LC);
    size_t base = m0 * NC + c;
    float H = g_Carry[j * LANES + lane];
#pragma unroll 8
    for (int t = 0; t < LC; t++) {
        float2 ab = Y2[base + (size_t)t * NC];
        H = fmaf(ab.x, H, ab.y);
        g_h[(m0 + t) * NC + c] = H;
    }
}

// ---------------- launch ----------------
// gemm1_mma is the 6th launch so ncu's `-s 5 -c 1` captures it.
extern "C" void kernel_launch(void* const* d_in, const int* in_sizes, int n_in,
                              void* d_out, int out_size) {
    const float* x   = (const float*)d_in[0];
    const float* Wzf = (const float*)d_in[1];
    const float* bzf = (const float*)d_in[2];
    const float* Whf = (const float*)d_in[3];
    const float* bhf = (const float*)d_in[4];
    const float* Wzs = (const float*)d_in[5];
    const float* bzs = (const float*)d_in[6];
    const float* Whs = (const float*)d_in[7];
    const float* bhs = (const float*)d_in[8];
    const float* Wg  = (const float*)d_in[9];
    const float* bg  = (const float*)d_in[10];
    float* out = (float*)d_out;

    dim3 tb(32, 32);
    transpose_pack_kernel<<<dim3(16, 32), tb>>>(Wzf, 512, 2, 0, 0);
    transpose_pack_kernel<<<dim3(16, 32), tb>>>(Whf, 512, 2, 1, 0);
    transpose_pack_kernel<<<dim3(16, 32), tb>>>(Wzs, 512, 2, 1024, 0);
    transpose_pack_kernel<<<dim3(16, 32), tb>>>(Whs, 512, 2, 1025, 0);
    pack_bias_kernel<<<N1 / 256, 256>>>(bzf, bhf, bzs, bhs);

    gemm1_mma<<<dim3(N1 / 128, M_ / 128), 128>>>(x);

    transpose_pack_kernel<<<dim3(32, 32), tb>>>(Wg, 1024, 1, 0, 1);

    scan_phase1<<<dim3(LANES / 256, NCHUNK), 256>>>();
    scan_phase2<<<LANES / 256, 256>>>();
    scan_phase3<<<dim3(LANES / 256, NCHUNK), 256>>>();

    gemm2_mma<<<dim3(NC / 128, M_ / 128), 128>>>(bg, out);
}